// round 4
// baseline (speedup 1.0000x reference)
#include <cuda_runtime.h>
#include <cuda_bf16.h>
#include <cstdint>

#define W 256
#define BH 32
#define NBLOCKS 1024          // 128 images * 8 bands
#define MAGSTRIDE 260         // floats per [slot][im] row of sh_mag
#define MAGSLOT  (2 * MAGSTRIDE)

__device__ float g_partials[NBLOCKS];
__device__ unsigned int g_ticket;   // zero-init; atomicInc wraps after NBLOCKS -> graph-replay safe

// Gaussian taps, computed as numpy does (f64 exp, f64 normalize, cast f32)
constexpr double E2d  = 0.1353352832366127;   // exp(-2)
constexpr double E05d = 0.6065306597126334;   // exp(-0.5)
constexpr double GSUM = 1.0 + 2.0 * (E2d + E05d);
constexpr float  G0 = (float)(E2d / GSUM);
constexpr float  G1 = (float)(E05d / GSUM);
constexpr float  G2 = (float)(1.0 / GSUM);

// Quadrant-exact tangent thresholds for k = 4 + round(atan2(gy,gx)*4/3.14159)
#define TLO_POS 0.414213174f
#define THI_POS 2.414206767f
#define TLO_NEG 0.414216283f
#define THI_NEG 2.414224887f

__device__ __forceinline__ int dir_idx(float gx, float gy) {
    float ax = fabsf(gx), ay = fabsf(gy);
    bool xn = gx < 0.0f;
    float tlo = xn ? TLO_NEG : TLO_POS;
    float thi = xn ? THI_NEG : THI_POS;
    int s = (ay >= ax * tlo) ? ((ay > ax * thi) ? 2 : 1) : 0;
    int kp = xn ? (4 - s) : s;
    int k = (gy < 0.0f) ? (4 - kp) : (4 + kp);
    return k & 7;
}

// NMS neighbor offsets packed in nibbles: (dr+1),(dc+1) per idx (validated rel_err=0)
#define DRP 0x00012221u
#define DCP 0x21000122u

// base points at sh_mag[0][im][col+2]; j == er&3 (compile-time)
__device__ __forceinline__ float nms_one(float m, int idx, const float* base, int j) {
    int dr = (int)((DRP >> (idx * 4)) & 3u) - 1;
    int dc = (int)((DCP >> (idx * 4)) & 3u) - 1;
    float np = base[((j + dr) & 3) * MAGSLOT + dc];
    float nn = base[((j - dr) & 3) * MAGSLOT - dc];
    return (fminf(m - np, m - nn) > 0.0f && m >= 2.0f) ? m : 0.0f;
}

// float4 layout in sh_prep / sh_bl and the register rings:
//   .x = img0 even col, .y = img0 odd col, .z = img1 even col, .w = img1 odd col
__global__ __launch_bounds__(128) void canny_fused(const float* __restrict__ in0,
                                                   const float* __restrict__ in1,
                                                   float* __restrict__ out) {
    const int t   = threadIdx.x;            // column-pair (cols 2t, 2t+1)
    const int blk = blockIdx.x;
    const int n   = blk >> 3;               // image
    const int r0  = (blk & 7) * BH;         // band start row (multiple of 32)
    const float* b0 = in0 + n * (W * W) + 2 * t;
    const float* b1 = in1 + n * (W * W) + 2 * t;

    __shared__ __align__(16) float4 sh_prep[2][130];   // pair p -> idx p+1; guards 0,129
    __shared__ __align__(16) float4 sh_bl[2][130];
    __shared__ __align__(16) float  sh_mag[4][2][MAGSTRIDE]; // col c -> idx c+2
    __shared__ float  red[128];
    __shared__ double sdd[128];
    __shared__ unsigned s_last;

    // zero everything once (guards stay zero; data cells get overwritten)
    {
        float4 z = make_float4(0.f, 0.f, 0.f, 0.f);
        float4* zp = (float4*)sh_prep;
        float4* zb = (float4*)sh_bl;
        float4* zm = (float4*)sh_mag;
        #pragma unroll
        for (int i = 0; i < 3; i++) { zp[t + 128 * i] = z; zb[t + 128 * i] = z; }
        if (t < 4)  { zp[384 + t] = z; zb[384 + t] = z; }
        #pragma unroll
        for (int i = 0; i < 4; i++) zm[t + 128 * i] = z;
        if (t < 8)  zm[512 + t] = z;
    }

    // register rings
    float4 hb0, hb1, hb2, hb3, hb4;                       // hblur rows ir-5..ir-1
    hb0 = hb1 = hb2 = hb3 = hb4 = make_float4(0.f, 0.f, 0.f, 0.f);
    float4 A0, A1, A2, Bx0, Bx1, Bx2;                     // Sobel row aggregates
    A0 = A1 = A2 = Bx0 = Bx1 = Bx2 = make_float4(0.f, 0.f, 0.f, 0.f);
    float4 d1m = make_float4(0.f, 0.f, 0.f, 0.f);
    float4 d2m = make_float4(0.f, 0.f, 0.f, 0.f);
    int d1i = 0, d2i = 0;                                 // packed 4x4-bit dir indices
    float acc = 0.f;

    const float* mbase0 = &sh_mag[0][0][2 * t + 2];
    const float* mbase1 = &sh_mag[0][1][2 * t + 2];

    __syncthreads();

    // 44 iterations: ir = r0-5 .. r0+BH+6.  r0 % 4 == 0  ->  ir mod 4 == (3+j) mod 4.
    for (int ir0 = r0 - 5; ir0 < r0 + BH + 7; ir0 += 4) {
        #pragma unroll
        for (int j = 0; j < 4; ++j) {
            const int ir = ir0 + j;
            const int sPrepW = (3 + j) & 1;       // slot for row ir
            const int sPrepR = (2 + j) & 1;       // slot holding row ir-1
            const int sBlW   = j & 1;             // slot for row ir-3
            const int sBlR   = (j + 1) & 1;       // slot holding row ir-4
            const int sMagW  = (j + 2) & 3;       // slot for row ir-5

            // global prefetch + prep (before barrier; LDG in flight across it)
            // CRITICAL: prep transform must be inside the guard — out-of-range rows
            // contribute exact 0.0 to the blur (round-3 bug stored (0+1)*0.5 = 0.5).
            float4 p = make_float4(0.f, 0.f, 0.f, 0.f);
            if ((unsigned)ir < (unsigned)W) {
                float2 q0 = *(const float2*)(b0 + ir * W);
                float2 q1 = *(const float2*)(b1 + ir * W);
                p = make_float4((q0.x + 1.0f) * 0.5f, (q0.y + 1.0f) * 0.5f,
                                (q1.x + 1.0f) * 0.5f, (q1.y + 1.0f) * 0.5f);
            }

            __syncthreads();

            sh_prep[sPrepW][t + 1] = p;

            // ---- hblur row ir-1 ----
            {
                const float4* pr = sh_prep[sPrepR];
                float4 e0 = pr[t], e1 = pr[t + 1], e2 = pr[t + 2];
                float4 h;
                h.x = G0 * (e0.x + e2.x) + G1 * (e0.y + e1.y) + G2 * e1.x;
                h.y = G0 * (e0.y + e2.y) + G1 * (e1.x + e2.x) + G2 * e1.y;
                h.z = G0 * (e0.z + e2.z) + G1 * (e0.w + e1.w) + G2 * e1.z;
                h.w = G0 * (e0.w + e2.w) + G1 * (e1.z + e2.z) + G2 * e1.w;
                hb0 = hb1; hb1 = hb2; hb2 = hb3; hb3 = hb4; hb4 = h;
            }

            // ---- vblur row br = ir-3 ----
            {
                const int br = ir - 3;
                float4 v = make_float4(0.f, 0.f, 0.f, 0.f);
                if ((unsigned)br < (unsigned)W) {
                    v.x = G0 * (hb0.x + hb4.x) + G1 * (hb1.x + hb3.x) + G2 * hb2.x;
                    v.y = G0 * (hb0.y + hb4.y) + G1 * (hb1.y + hb3.y) + G2 * hb2.y;
                    v.z = G0 * (hb0.z + hb4.z) + G1 * (hb1.z + hb3.z) + G2 * hb2.z;
                    v.w = G0 * (hb0.w + hb4.w) + G1 * (hb1.w + hb3.w) + G2 * hb2.w;
                }
                sh_bl[sBlW][t + 1] = v;
            }

            // ---- Sobel row aggregates for row ir-4 ----
            {
                const float4* bl = sh_bl[sBlR];
                float4 f0 = bl[t], f1 = bl[t + 1], f2 = bl[t + 2];
                float4 A, Bv;
                A.x  = f0.y + 2.0f * f1.x + f1.y;   Bv.x = f0.y - f1.y;
                A.y  = f1.x + 2.0f * f1.y + f2.x;   Bv.y = f1.x - f2.x;
                A.z  = f0.w + 2.0f * f1.z + f1.w;   Bv.z = f0.w - f1.w;
                A.w  = f1.z + 2.0f * f1.w + f2.z;   Bv.w = f1.z - f2.z;
                A0 = A1; A1 = A2; A2 = A;
                Bx0 = Bx1; Bx1 = Bx2; Bx2 = Bv;
            }

            // ---- Sobel + magnitude + orientation for row mr = ir-5 ----
            float4 nm = make_float4(0.f, 0.f, 0.f, 0.f);
            int ni = 0;
            {
                const int mr = ir - 5;
                if ((unsigned)mr < (unsigned)W) {
                    float gx, gy;
                    gx = Bx0.x + 2.0f * Bx1.x + Bx2.x;  gy = A0.x - A2.x;
                    nm.x = sqrtf(gx * gx + gy * gy);    ni  = dir_idx(gx, gy);
                    gx = Bx0.y + 2.0f * Bx1.y + Bx2.y;  gy = A0.y - A2.y;
                    nm.y = sqrtf(gx * gx + gy * gy);    ni |= dir_idx(gx, gy) << 4;
                    gx = Bx0.z + 2.0f * Bx1.z + Bx2.z;  gy = A0.z - A2.z;
                    nm.z = sqrtf(gx * gx + gy * gy);    ni |= dir_idx(gx, gy) << 8;
                    gx = Bx0.w + 2.0f * Bx1.w + Bx2.w;  gy = A0.w - A2.w;
                    nm.w = sqrtf(gx * gx + gy * gy);    ni |= dir_idx(gx, gy) << 12;
                }
                *(float2*)&sh_mag[sMagW][0][2 * t + 2] = make_float2(nm.x, nm.y);
                *(float2*)&sh_mag[sMagW][1][2 * t + 2] = make_float2(nm.z, nm.w);
            }

            // ---- NMS + threshold + |diff| for row er = ir-7 (er&3 == j) ----
            {
                const int er = ir - 7;
                if (er >= r0 && er < r0 + BH) {
                    float e0e = nms_one(d2m.x, (d2i >> 0)  & 7, mbase0,     j);
                    float e0o = nms_one(d2m.y, (d2i >> 4)  & 7, mbase0 + 1, j);
                    float e1e = nms_one(d2m.z, (d2i >> 8)  & 7, mbase1,     j);
                    float e1o = nms_one(d2m.w, (d2i >> 12) & 7, mbase1 + 1, j);
                    acc += fabsf(e0e - e1e) + fabsf(e0o - e1o);
                }
            }

            d2m = d1m; d1m = nm;
            d2i = d1i; d1i = ni;
        }
    }

    // deterministic block reduction
    red[t] = acc;
    __syncthreads();
    #pragma unroll
    for (int off = 64; off > 0; off >>= 1) {
        if (t < off) red[t] += red[t + off];
        __syncthreads();
    }

    if (t == 0) {
        g_partials[blk] = red[0];
        __threadfence();
        unsigned old = atomicInc(&g_ticket, NBLOCKS - 1);   // wraps to 0 -> replay-safe
        s_last = (old == NBLOCKS - 1) ? 1u : 0u;
    }
    __syncthreads();

    // last block deterministically reduces all partials (double precision)
    if (s_last) {
        double s = 0.0;
        for (int i = t; i < NBLOCKS; i += 128) s += (double)__ldcg(&g_partials[i]);
        sdd[t] = s;
        __syncthreads();
        #pragma unroll
        for (int off = 64; off > 0; off >>= 1) {
            if (t < off) sdd[t] += sdd[t + off];
            __syncthreads();
        }
        if (t == 0) out[0] = (float)(sdd[0] / 8388608.0);
    }
}

extern "C" void kernel_launch(void* const* d_in, const int* in_sizes, int n_in,
                              void* d_out, int out_size) {
    const float* gt = (const float*)d_in[0];   // data_input
    const float* pr = (const float*)d_in[1];   // model_output
    canny_fused<<<NBLOCKS, 128>>>(gt, pr, (float*)d_out);
}

// round 5
// speedup vs baseline: 1.0541x; 1.0541x over previous
#include <cuda_runtime.h>
#include <cuda_bf16.h>
#include <cstdint>

#define W 256
#define BH 32
#define NBLOCKS 1024          // 128 images * 8 bands
#define MAGF 516              // floats per mag slot (258 float2)

__device__ float g_partials[NBLOCKS];
__device__ unsigned int g_ticket;   // zero-init; atomicInc wraps after NBLOCKS -> graph-replay safe

// Gaussian taps, computed as numpy does (f64 exp, f64 normalize, cast f32)
constexpr double E2d  = 0.1353352832366127;   // exp(-2)
constexpr double E05d = 0.6065306597126334;   // exp(-0.5)
constexpr double GSUM = 1.0 + 2.0 * (E2d + E05d);
constexpr float  G0 = (float)(E2d / GSUM);
constexpr float  G1 = (float)(E05d / GSUM);
constexpr float  G2 = (float)(1.0 / GSUM);

// Quadrant-exact tangent thresholds for k = 4 + round(atan2(gy,gx)*4/3.14159)
#define TLO_POS 0.414213174f
#define THI_POS 2.414206767f
#define TLO_NEG 0.414216283f
#define THI_NEG 2.414224887f

__device__ __forceinline__ int dir_idx(float gx, float gy) {
    float ax = fabsf(gx), ay = fabsf(gy);
    bool xn = gx < 0.0f;
    float tlo = xn ? TLO_NEG : TLO_POS;
    float thi = xn ? THI_NEG : THI_POS;
    int s = (ay >= ax * tlo) ? ((ay > ax * thi) ? 2 : 1) : 0;
    int kp = xn ? (4 - s) : s;
    int k = (gy < 0.0f) ? (4 - kp) : (4 + kp);
    return k & 7;
}

// NMS neighbor offsets packed in nibbles: (dr+1),(dc+1) per idx (validated rel_err=0)
#define DRP 0x00012221u
#define DCP 0x21000122u

// base points at float component (img) of sh_mag[0][t+1]; j == er&3 (compile-time)
__device__ __forceinline__ float nms_one(float m, int idx, const float* base, int j) {
    int dr = (int)((DRP >> (idx * 4)) & 3u) - 1;
    int dc = (int)((DCP >> (idx * 4)) & 3u) - 1;
    float np = base[((j + dr) & 3) * MAGF + 2 * dc];
    float nn = base[((j - dr) & 3) * MAGF - 2 * dc];
    return (fminf(m - np, m - nn) > 0.0f && m >= 2.0f) ? m : 0.0f;
}

// float2 layout everywhere: .x = image0, .y = image1
__global__ __launch_bounds__(256) void canny_fused(const float* __restrict__ in0,
                                                   const float* __restrict__ in1,
                                                   float* __restrict__ out) {
    const int t   = threadIdx.x;            // column
    const int blk = blockIdx.x;
    const int n   = blk >> 3;               // image
    const int r0  = (blk & 7) * BH;         // band start row (multiple of 32)
    const float* b0 = in0 + n * (W * W) + t;
    const float* b1 = in1 + n * (W * W) + t;

    __shared__ __align__(8) float2 sh_prep[2][W + 4];   // col c -> idx c+2; guards 0,1,258,259
    __shared__ __align__(8) float2 sh_bl[2][W + 2];     // col c -> idx c+1; guards 0,257
    __shared__ __align__(8) float2 sh_mag[4][W + 2];    // col c -> idx c+1; guards 0,257
    __shared__ float  red[256];
    __shared__ double sdd[256];
    __shared__ unsigned s_last;

    // zero everything once (guards stay zero; data cells get overwritten)
    {
        float2 z = make_float2(0.f, 0.f);
        float2* zp = (float2*)sh_prep;
        for (int i = t; i < 2 * (W + 4); i += 256) zp[i] = z;
        float2* zb = (float2*)sh_bl;
        for (int i = t; i < 2 * (W + 2); i += 256) zb[i] = z;
        float2* zm = (float2*)sh_mag;
        for (int i = t; i < 4 * (W + 2); i += 256) zm[i] = z;
    }

    // register rings
    float2 hb0, hb1, hb2, hb3, hb4;                       // hblur rows ir-5..ir-1
    hb0 = hb1 = hb2 = hb3 = hb4 = make_float2(0.f, 0.f);
    float2 A0, A1, A2, Bx0, Bx1, Bx2;                     // Sobel row aggregates
    A0 = A1 = A2 = Bx0 = Bx1 = Bx2 = make_float2(0.f, 0.f);
    float2 d1m = make_float2(0.f, 0.f);
    float2 d2m = make_float2(0.f, 0.f);
    int d1i = 0, d2i = 0;                                 // packed 2x4-bit dir indices
    float acc = 0.f;

    const float* mbase0 = &sh_mag[0][t + 1].x;
    const float* mbase1 = &sh_mag[0][t + 1].y;

    __syncthreads();

    // 44 iterations: ir = r0-5 .. r0+BH+6.  r0 % 4 == 0  ->  ir mod 4 == (j+3) & 3.
    // Pipeline: load ir | hblur ir-1 | vblur ir-3 | A/B ir-4 | mag ir-5 | NMS ir-7.
    // All ring-slot indices below are compile-time constants of j.
    #pragma unroll 1
    for (int ir0 = r0 - 5; ir0 < r0 + BH + 7; ir0 += 4) {
        #pragma unroll
        for (int j = 0; j < 4; ++j) {
            const int ir = ir0 + j;
            const int sPrepW = (j + 1) & 1;   // slot for row ir       (ir & 1)
            const int sPrepR = j & 1;         // slot of row ir-1
            const int sBlW   = j & 1;         // slot for row ir-3     ((ir-3) & 1)
            const int sBlR   = (j + 1) & 1;   // slot of row ir-4
            const int sMagW  = (j + 2) & 3;   // slot for row ir-5     ((ir-5) & 3)

            // global prefetch + prep BEFORE the barrier (LDG in flight across it).
            // Prep transform inside the guard: out-of-range rows contribute exact 0.
            float2 p = make_float2(0.f, 0.f);
            if ((unsigned)ir < (unsigned)W) {
                float q0 = b0[ir * W];
                float q1 = b1[ir * W];
                p = make_float2((q0 + 1.0f) * 0.5f, (q1 + 1.0f) * 0.5f);
            }

            __syncthreads();   // single barrier: prior-iter reads | this-iter writes

            sh_prep[sPrepW][t + 2] = p;

            // ---- hblur row ir-1 ----
            {
                const float2* pr = sh_prep[sPrepR];
                float2 a0 = pr[t], a1 = pr[t + 1], a2 = pr[t + 2], a3 = pr[t + 3], a4 = pr[t + 4];
                float2 h;
                h.x = G0 * (a0.x + a4.x) + G1 * (a1.x + a3.x) + G2 * a2.x;
                h.y = G0 * (a0.y + a4.y) + G1 * (a1.y + a3.y) + G2 * a2.y;
                hb0 = hb1; hb1 = hb2; hb2 = hb3; hb3 = hb4; hb4 = h;
            }

            // ---- vblur row br = ir-3 ----
            {
                const int br = ir - 3;
                float2 v = make_float2(0.f, 0.f);
                if ((unsigned)br < (unsigned)W) {
                    v.x = G0 * (hb0.x + hb4.x) + G1 * (hb1.x + hb3.x) + G2 * hb2.x;
                    v.y = G0 * (hb0.y + hb4.y) + G1 * (hb1.y + hb3.y) + G2 * hb2.y;
                }
                sh_bl[sBlW][t + 1] = v;
            }

            // ---- Sobel row aggregates for row ir-4 ----
            {
                const float2* bl = sh_bl[sBlR];
                float2 l = bl[t], c = bl[t + 1], r = bl[t + 2];
                float2 A, Bv;
                A.x  = l.x + 2.0f * c.x + r.x;   Bv.x = l.x - r.x;
                A.y  = l.y + 2.0f * c.y + r.y;   Bv.y = l.y - r.y;
                A0 = A1; A1 = A2; A2 = A;
                Bx0 = Bx1; Bx1 = Bx2; Bx2 = Bv;
            }

            // ---- Sobel + magnitude + orientation for row mr = ir-5 ----
            float2 nm = make_float2(0.f, 0.f);
            int ni = 0;
            {
                const int mr = ir - 5;
                if ((unsigned)mr < (unsigned)W) {
                    float gx0 = Bx0.x + 2.0f * Bx1.x + Bx2.x;
                    float gy0 = A0.x - A2.x;
                    nm.x = sqrtf(gx0 * gx0 + gy0 * gy0);
                    ni   = dir_idx(gx0, gy0);
                    float gx1 = Bx0.y + 2.0f * Bx1.y + Bx2.y;
                    float gy1 = A0.y - A2.y;
                    nm.y = sqrtf(gx1 * gx1 + gy1 * gy1);
                    ni  |= dir_idx(gx1, gy1) << 4;
                }
                sh_mag[sMagW][t + 1] = nm;
            }

            // ---- NMS + threshold + |diff| for row er = ir-7 (er mod 4 == j) ----
            {
                const int er = ir - 7;
                if (er >= r0 && er < r0 + BH) {
                    float e0 = nms_one(d2m.x, d2i & 7,        mbase0, j);
                    float e1 = nms_one(d2m.y, (d2i >> 4) & 7, mbase1, j);
                    acc += fabsf(e0 - e1);
                }
            }

            d2m = d1m; d1m = nm;
            d2i = d1i; d1i = ni;
        }
    }

    // deterministic block reduction
    red[t] = acc;
    __syncthreads();
    #pragma unroll
    for (int off = 128; off > 0; off >>= 1) {
        if (t < off) red[t] += red[t + off];
        __syncthreads();
    }

    if (t == 0) {
        g_partials[blk] = red[0];
        __threadfence();
        unsigned old = atomicInc(&g_ticket, NBLOCKS - 1);   // wraps to 0 -> replay-safe
        s_last = (old == NBLOCKS - 1) ? 1u : 0u;
    }
    __syncthreads();

    // last block deterministically reduces all partials (double precision)
    if (s_last) {
        double s = 0.0;
        for (int i = t; i < NBLOCKS; i += 256) s += (double)__ldcg(&g_partials[i]);
        sdd[t] = s;
        __syncthreads();
        #pragma unroll
        for (int off = 128; off > 0; off >>= 1) {
            if (t < off) sdd[t] += sdd[t + off];
            __syncthreads();
        }
        if (t == 0) out[0] = (float)(sdd[0] / 8388608.0);
    }
}

extern "C" void kernel_launch(void* const* d_in, const int* in_sizes, int n_in,
                              void* d_out, int out_size) {
    const float* gt = (const float*)d_in[0];   // data_input
    const float* pr = (const float*)d_in[1];   // model_output
    canny_fused<<<NBLOCKS, 256>>>(gt, pr, (float*)d_out);
}

// round 6
// speedup vs baseline: 1.3780x; 1.3073x over previous
#include <cuda_runtime.h>
#include <cuda_bf16.h>
#include <cstdint>

#define W 256
#define BH 32
#define NBLOCKS 1024          // 128 images * 8 bands
#define MAGF 516              // floats per mag slot (258 float2)

__device__ float g_partials[NBLOCKS];
__device__ unsigned int g_ticket;   // zero-init; atomicInc wraps after NBLOCKS -> graph-replay safe

// Gaussian taps, computed as numpy does (f64 exp, f64 normalize, cast f32)
constexpr double E2d  = 0.1353352832366127;   // exp(-2)
constexpr double E05d = 0.6065306597126334;   // exp(-0.5)
constexpr double GSUM = 1.0 + 2.0 * (E2d + E05d);
constexpr float  G0 = (float)(E2d / GSUM);
constexpr float  G1 = (float)(E05d / GSUM);
constexpr float  G2 = (float)(1.0 / GSUM);

// Quadrant-exact tangent thresholds for k = 4 + round(atan2(gy,gx)*4/3.14159)
#define TLO_POS 0.414213174f
#define THI_POS 2.414206767f
#define TLO_NEG 0.414216283f
#define THI_NEG 2.414224887f

__device__ __forceinline__ int dir_idx(float gx, float gy) {
    float ax = fabsf(gx), ay = fabsf(gy);
    bool xn = gx < 0.0f;
    float tlo = xn ? TLO_NEG : TLO_POS;
    float thi = xn ? THI_NEG : THI_POS;
    int s = (ay >= ax * tlo) ? ((ay > ax * thi) ? 2 : 1) : 0;
    int kp = xn ? (4 - s) : s;
    int k = (gy < 0.0f) ? (4 - kp) : (4 + kp);
    return k & 7;
}

// NMS neighbor offsets packed in nibbles: (dr+1),(dc+1) per idx (validated rel_err=0)
#define DRP 0x00012221u
#define DCP 0x21000122u

// Operates on SQUARED magnitudes. sqrtf only on pass (rare).
// Monotonicity: sqrt correctly rounded => m>np iff msq>npsq (ties measure-zero),
// and sqrt(msq)>=2 iff msq>=4 exactly.
__device__ __forceinline__ float nms_one(float msq, int idx, const float* base, int j) {
    int dr = (int)((DRP >> (idx * 4)) & 3u) - 1;
    int dc = (int)((DCP >> (idx * 4)) & 3u) - 1;
    float np = base[((j + dr) & 3) * MAGF + 2 * dc];
    float nn = base[((j - dr) & 3) * MAGF - 2 * dc];
    bool pass = (fminf(msq - np, msq - nn) > 0.0f) && (msq >= 4.0f);
    return pass ? sqrtf(msq) : 0.0f;
}

// float2 layout everywhere: .x = image0, .y = image1
__global__ __launch_bounds__(256) void canny_fused(const float* __restrict__ in0,
                                                   const float* __restrict__ in1,
                                                   float* __restrict__ out) {
    const int t   = threadIdx.x;            // column
    const int blk = blockIdx.x;
    const int n   = blk >> 3;               // image
    const int r0  = (blk & 7) * BH;         // band start row (multiple of 32)
    const float* b0 = in0 + n * (W * W) + t;
    const float* b1 = in1 + n * (W * W) + t;

    __shared__ __align__(8) float2 sh_prep[2][W + 4];   // col c -> idx c+2; guards 0,1,258,259
    __shared__ __align__(8) float2 sh_bl[2][W + 2];     // col c -> idx c+1; guards 0,257
    __shared__ __align__(8) float2 sh_mag[4][W + 2];    // SQUARED mags; col c -> idx c+1
    __shared__ float  red[256];
    __shared__ double sdd[256];
    __shared__ unsigned s_last;

    // zero everything once (guards stay zero; data cells get overwritten)
    {
        float2 z = make_float2(0.f, 0.f);
        float2* zp = (float2*)sh_prep;
        for (int i = t; i < 2 * (W + 4); i += 256) zp[i] = z;
        float2* zb = (float2*)sh_bl;
        for (int i = t; i < 2 * (W + 2); i += 256) zb[i] = z;
        float2* zm = (float2*)sh_mag;
        for (int i = t; i < 4 * (W + 2); i += 256) zm[i] = z;
    }

    // register rings
    float2 hb0, hb1, hb2, hb3, hb4;                       // hblur rows ir-5..ir-1
    hb0 = hb1 = hb2 = hb3 = hb4 = make_float2(0.f, 0.f);
    float2 A0, A1, A2, Bx0, Bx1, Bx2;                     // Sobel row aggregates
    A0 = A1 = A2 = Bx0 = Bx1 = Bx2 = make_float2(0.f, 0.f);
    float2 d1m = make_float2(0.f, 0.f);                   // delayed mag^2
    float2 d2m = make_float2(0.f, 0.f);
    float4 d1g = make_float4(0.f, 0.f, 0.f, 0.f);         // delayed (gx0,gy0,gx1,gy1)
    float4 d2g = make_float4(0.f, 0.f, 0.f, 0.f);
    float acc = 0.f;

    const float* mbase0 = &sh_mag[0][t + 1].x;
    const float* mbase1 = &sh_mag[0][t + 1].y;

    __syncthreads();

    // 44 iterations: ir = r0-5 .. r0+BH+6.  r0 % 4 == 0  ->  ir mod 4 == (j+3) & 3.
    // Pipeline: load ir | hblur ir-1 | vblur ir-3 | A/B ir-4 | magsq ir-5 | NMS ir-7.
    #pragma unroll 1
    for (int ir0 = r0 - 5; ir0 < r0 + BH + 7; ir0 += 4) {
        #pragma unroll
        for (int j = 0; j < 4; ++j) {
            const int ir = ir0 + j;
            const int sPrepW = (j + 1) & 1;   // slot for row ir       (ir & 1)
            const int sPrepR = j & 1;         // slot of row ir-1
            const int sBlW   = j & 1;         // slot for row ir-3     ((ir-3) & 1)
            const int sBlR   = (j + 1) & 1;   // slot of row ir-4
            const int sMagW  = (j + 2) & 3;   // slot for row ir-5     ((ir-5) & 3)

            // global prefetch + prep BEFORE the barrier (LDG in flight across it).
            // Prep transform inside the guard: out-of-range rows contribute exact 0.
            float2 p = make_float2(0.f, 0.f);
            if ((unsigned)ir < (unsigned)W) {
                float q0 = b0[ir * W];
                float q1 = b1[ir * W];
                p = make_float2((q0 + 1.0f) * 0.5f, (q1 + 1.0f) * 0.5f);
            }

            __syncthreads();   // single barrier: prior-iter reads | this-iter writes

            sh_prep[sPrepW][t + 2] = p;

            // ---- hblur row ir-1 ----
            {
                const float2* pr = sh_prep[sPrepR];
                float2 a0 = pr[t], a1 = pr[t + 1], a2 = pr[t + 2], a3 = pr[t + 3], a4 = pr[t + 4];
                float2 h;
                h.x = G0 * (a0.x + a4.x) + G1 * (a1.x + a3.x) + G2 * a2.x;
                h.y = G0 * (a0.y + a4.y) + G1 * (a1.y + a3.y) + G2 * a2.y;
                hb0 = hb1; hb1 = hb2; hb2 = hb3; hb3 = hb4; hb4 = h;
            }

            // ---- vblur row br = ir-3 ----
            {
                const int br = ir - 3;
                float2 v = make_float2(0.f, 0.f);
                if ((unsigned)br < (unsigned)W) {
                    v.x = G0 * (hb0.x + hb4.x) + G1 * (hb1.x + hb3.x) + G2 * hb2.x;
                    v.y = G0 * (hb0.y + hb4.y) + G1 * (hb1.y + hb3.y) + G2 * hb2.y;
                }
                sh_bl[sBlW][t + 1] = v;
            }

            // ---- Sobel row aggregates for row ir-4 ----
            {
                const float2* bl = sh_bl[sBlR];
                float2 l = bl[t], c = bl[t + 1], r = bl[t + 2];
                float2 A, Bv;
                A.x  = l.x + 2.0f * c.x + r.x;   Bv.x = l.x - r.x;
                A.y  = l.y + 2.0f * c.y + r.y;   Bv.y = l.y - r.y;
                A0 = A1; A1 = A2; A2 = A;
                Bx0 = Bx1; Bx1 = Bx2; Bx2 = Bv;
            }

            // ---- Sobel + SQUARED magnitude for row mr = ir-5 (no sqrt, no dir here) ----
            float2 nm = make_float2(0.f, 0.f);
            float4 ng = make_float4(0.f, 0.f, 0.f, 0.f);
            {
                const int mr = ir - 5;
                if ((unsigned)mr < (unsigned)W) {
                    ng.x = Bx0.x + 2.0f * Bx1.x + Bx2.x;   // gx0
                    ng.y = A0.x - A2.x;                    // gy0
                    nm.x = ng.x * ng.x + ng.y * ng.y;
                    ng.z = Bx0.y + 2.0f * Bx1.y + Bx2.y;   // gx1
                    ng.w = A0.y - A2.y;                    // gy1
                    nm.y = ng.z * ng.z + ng.w * ng.w;
                }
                sh_mag[sMagW][t + 1] = nm;
            }

            // ---- NMS + threshold + |diff| for row er = ir-7 (er mod 4 == j) ----
            // Warp-uniform skip: direction decode, gather and sqrt only run if some
            // lane in the warp can possibly pass the threshold (msq >= 4).
            {
                const int er = ir - 7;
                if (er >= r0 && er < r0 + BH) {
                    float mx = fmaxf(d2m.x, d2m.y);
                    if (__any_sync(0xffffffffu, mx >= 4.0f)) {
                        int i0 = dir_idx(d2g.x, d2g.y);
                        int i1 = dir_idx(d2g.z, d2g.w);
                        float e0 = nms_one(d2m.x, i0, mbase0, j);
                        float e1 = nms_one(d2m.y, i1, mbase1, j);
                        acc += fabsf(e0 - e1);
                    }
                }
            }

            d2m = d1m; d1m = nm;
            d2g = d1g; d1g = ng;
        }
    }

    // deterministic block reduction
    red[t] = acc;
    __syncthreads();
    #pragma unroll
    for (int off = 128; off > 0; off >>= 1) {
        if (t < off) red[t] += red[t + off];
        __syncthreads();
    }

    if (t == 0) {
        g_partials[blk] = red[0];
        __threadfence();
        unsigned old = atomicInc(&g_ticket, NBLOCKS - 1);   // wraps to 0 -> replay-safe
        s_last = (old == NBLOCKS - 1) ? 1u : 0u;
    }
    __syncthreads();

    // last block deterministically reduces all partials (double precision)
    if (s_last) {
        double s = 0.0;
        for (int i = t; i < NBLOCKS; i += 256) s += (double)__ldcg(&g_partials[i]);
        sdd[t] = s;
        __syncthreads();
        #pragma unroll
        for (int off = 128; off > 0; off >>= 1) {
            if (t < off) sdd[t] += sdd[t + off];
            __syncthreads();
        }
        if (t == 0) out[0] = (float)(sdd[0] / 8388608.0);
    }
}

extern "C" void kernel_launch(void* const* d_in, const int* in_sizes, int n_in,
                              void* d_out, int out_size) {
    const float* gt = (const float*)d_in[0];   // data_input
    const float* pr = (const float*)d_in[1];   // model_output
    canny_fused<<<NBLOCKS, 256>>>(gt, pr, (float*)d_out);
}